// round 11
// baseline (speedup 1.0000x reference)
#include <cuda_runtime.h>
#include <cuda_bf16.h>
#include <cstdint>
#include <cstddef>

#define NN 4096
#define DD 128
#define EPS 1e-12f
#define SLOTS 512            // per-row edge slots (mean 244, 17-sigma safe)

#define GRIDE 1332           // edge blocks (x8 warps)

// ---------------- scratch (__device__ globals; no allocs allowed) ----------
__device__ float g_feat[NN * DD];                       // W @ activities (fp32)
__device__ __nv_bfloat16 g_featbf[NN * DD];             // bf16 copy for SpMM gathers
__device__ __nv_bfloat16 g_Abf[NN * DD];                // activities bf16 (edge gathers)
__device__ __nv_bfloat16 g_Bh[DD * NN], g_Bl[DD * NN];  // activities^T split [N][K]
__device__ float2 g_ent[(size_t)NN * SLOTS];            // (col,val) per row, 16 MB
__device__ int g_cursor[NN];
__device__ int g_is64;

// ---------------------------------------------------------------------------
// detect: independent loads (MLP 64), no serial break chain
// ---------------------------------------------------------------------------
__global__ void detect_kernel(const unsigned int* __restrict__ w) {
    int lane = threadIdx.x;
    unsigned int acc = w[2 * lane + 1] | w[2 * (lane + 32) + 1];
#pragma unroll
    for (int o = 16; o > 0; o >>= 1) acc |= __shfl_xor_sync(0xffffffffu, acc, o);
    if (lane == 0) g_is64 = (acc == 0u) ? 1 : 0;
}

// ---------------------------------------------------------------------------
// prep: A [4096,128] fp32 -> g_Bh/g_Bl [128,4096] split ([N][K]) + g_Abf bf16
// ---------------------------------------------------------------------------
__global__ void prep_kernel(const float* __restrict__ src) {
    __shared__ float tile[32][33];
    int k0 = blockIdx.x * 32, n0 = blockIdx.y * 32;
    int tx = threadIdx.x, ty = threadIdx.y;
#pragma unroll
    for (int i = 0; i < 4; i++) {
        size_t idx = (size_t)(k0 + ty + i * 8) * DD + n0 + tx;
        float v = src[idx];
        tile[ty + i * 8][tx] = v;
        g_Abf[idx] = __float2bfloat16_rn(v);
    }
    __syncthreads();
#pragma unroll
    for (int i = 0; i < 4; i++) {
        float x = tile[tx][ty + i * 8];
        __nv_bfloat16 h = __float2bfloat16_rn(x);
        __nv_bfloat16 l = __float2bfloat16_rn(x - __bfloat162float(h));
        size_t o = (size_t)(n0 + ty + i * 8) * NN + k0 + tx;
        g_Bh[o] = h;
        g_Bl[o] = l;
    }
}

// ---------------------------------------------------------------------------
#define PITCHB 144           // bytes per smem row (72 bf16: +8 pad, conflict-free)
#define SM_AH 0
#define SM_AL (64 * PITCHB)
#define SM_BH (2 * 64 * PITCHB)
#define SM_BL (2 * 64 * PITCHB + 128 * PITCHB)
#define SMEM_GEMM (2 * 64 * PITCHB + 2 * 128 * PITCHB)   // 55296 B

__device__ __forceinline__ void mma_bf16(float* c, const uint32_t* a, const uint32_t* b) {
    asm volatile(
        "mma.sync.aligned.m16n8k16.row.col.f32.bf16.bf16.f32 "
        "{%0,%1,%2,%3}, {%4,%5,%6,%7}, {%8,%9}, {%0,%1,%2,%3};"
        : "+f"(c[0]), "+f"(c[1]), "+f"(c[2]), "+f"(c[3])
        : "r"(a[0]), "r"(a[1]), "r"(a[2]), "r"(a[3]), "r"(b[0]), "r"(b[1]));
}

// ---------------------------------------------------------------------------
// Warp-MMA split-bf16 GEMM: g_feat[m0:m0+64][:] += W_tile @ B^T (split-K x4)
// ---------------------------------------------------------------------------
__global__ __launch_bounds__(256, 2)
void gemm_mma_kernel(const float* __restrict__ Amat,
                     const __nv_bfloat16* __restrict__ Bh,
                     const __nv_bfloat16* __restrict__ Bl,
                     float* __restrict__ outacc) {
    extern __shared__ char smem[];
    const int tid = threadIdx.x;
    const int wid = tid >> 5, lane = tid & 31;
    const int warp_m = wid >> 2, warp_n = wid & 3;   // 2 x 4
    const int lr = lane >> 2, lc = lane & 3;
    const int m0 = ((int)blockIdx.x >> 2) * 64;
    const int kbase = ((int)blockIdx.x & 3) * 1024;

    const int a_row = tid >> 4;
    const int a_c4 = tid & 15;

    float acc[2][4][4];
#pragma unroll
    for (int i = 0; i < 2; i++)
#pragma unroll
        for (int j = 0; j < 4; j++)
#pragma unroll
            for (int q = 0; q < 4; q++) acc[i][j][q] = 0.f;

    for (int ch = 0; ch < 16; ch++) {
        int k0 = kbase + ch * 64;
        float4 av[4];
#pragma unroll
        for (int i = 0; i < 4; i++)
            av[i] = *(const float4*)&Amat[(size_t)(m0 + a_row + i * 16) * NN + k0 + a_c4 * 4];
        uint4 bhv[4], blv[4];
#pragma unroll
        for (int i = 0; i < 4; i++) {
            int idx = tid + i * 256;
            int n = idx >> 3, q = idx & 7;
            size_t byt = ((size_t)n * NN + k0) * 2 + q * 16;
            bhv[i] = *(const uint4*)((const char*)Bh + byt);
            blv[i] = *(const uint4*)((const char*)Bl + byt);
        }
        if (ch > 0) __syncthreads();
#pragma unroll
        for (int i = 0; i < 4; i++) {
            float4 v = av[i];
            __nv_bfloat16 h0 = __float2bfloat16_rn(v.x);
            __nv_bfloat16 h1 = __float2bfloat16_rn(v.y);
            __nv_bfloat16 h2 = __float2bfloat16_rn(v.z);
            __nv_bfloat16 h3 = __float2bfloat16_rn(v.w);
            __nv_bfloat16 l0 = __float2bfloat16_rn(v.x - __bfloat162float(h0));
            __nv_bfloat16 l1 = __float2bfloat16_rn(v.y - __bfloat162float(h1));
            __nv_bfloat16 l2 = __float2bfloat16_rn(v.z - __bfloat162float(h2));
            __nv_bfloat16 l3 = __float2bfloat16_rn(v.w - __bfloat162float(h3));
            uint2 hp, lp;
            hp.x = ((uint32_t)__bfloat16_as_ushort(h1) << 16) | __bfloat16_as_ushort(h0);
            hp.y = ((uint32_t)__bfloat16_as_ushort(h3) << 16) | __bfloat16_as_ushort(h2);
            lp.x = ((uint32_t)__bfloat16_as_ushort(l1) << 16) | __bfloat16_as_ushort(l0);
            lp.y = ((uint32_t)__bfloat16_as_ushort(l3) << 16) | __bfloat16_as_ushort(l2);
            uint32_t off = (uint32_t)(a_row + i * 16) * PITCHB + a_c4 * 8;
            *(uint2*)(smem + SM_AH + off) = hp;
            *(uint2*)(smem + SM_AL + off) = lp;
        }
#pragma unroll
        for (int i = 0; i < 4; i++) {
            int idx = tid + i * 256;
            int n = idx >> 3, q = idx & 7;
            uint32_t off = (uint32_t)n * PITCHB + q * 16;
            *(uint4*)(smem + SM_BH + off) = bhv[i];
            *(uint4*)(smem + SM_BL + off) = blv[i];
        }
        __syncthreads();
#pragma unroll
        for (int k16 = 0; k16 < 4; k16++) {
            uint32_t a_h[2][4], a_l[2][4];
#pragma unroll
            for (int mt = 0; mt < 2; mt++) {
                uint32_t base = (uint32_t)(warp_m * 32 + mt * 16 + lr) * PITCHB
                                + k16 * 32 + lc * 4;
                a_h[mt][0] = *(const uint32_t*)(smem + SM_AH + base);
                a_h[mt][1] = *(const uint32_t*)(smem + SM_AH + base + 8 * PITCHB);
                a_h[mt][2] = *(const uint32_t*)(smem + SM_AH + base + 16);
                a_h[mt][3] = *(const uint32_t*)(smem + SM_AH + base + 8 * PITCHB + 16);
                a_l[mt][0] = *(const uint32_t*)(smem + SM_AL + base);
                a_l[mt][1] = *(const uint32_t*)(smem + SM_AL + base + 8 * PITCHB);
                a_l[mt][2] = *(const uint32_t*)(smem + SM_AL + base + 16);
                a_l[mt][3] = *(const uint32_t*)(smem + SM_AL + base + 8 * PITCHB + 16);
            }
#pragma unroll
            for (int nt = 0; nt < 4; nt++) {
                uint32_t b_h[2], b_l[2];
                uint32_t base = (uint32_t)(warp_n * 32 + nt * 8 + lr) * PITCHB
                                + k16 * 32 + lc * 4;
                b_h[0] = *(const uint32_t*)(smem + SM_BH + base);
                b_h[1] = *(const uint32_t*)(smem + SM_BH + base + 16);
                b_l[0] = *(const uint32_t*)(smem + SM_BL + base);
                b_l[1] = *(const uint32_t*)(smem + SM_BL + base + 16);
#pragma unroll
                for (int mt = 0; mt < 2; mt++) {
                    mma_bf16(acc[mt][nt], a_h[mt], b_h);
                    mma_bf16(acc[mt][nt], a_h[mt], b_l);
                    mma_bf16(acc[mt][nt], a_l[mt], b_h);
                }
            }
        }
    }
#pragma unroll
    for (int mt = 0; mt < 2; mt++) {
#pragma unroll
        for (int nt = 0; nt < 4; nt++) {
            int row = m0 + warp_m * 32 + mt * 16 + lr;
            int col = warp_n * 32 + nt * 8 + lc * 2;
            atomicAdd(&outacc[(size_t)row * DD + col], acc[mt][nt][0]);
            atomicAdd(&outacc[(size_t)row * DD + col + 1], acc[mt][nt][1]);
            atomicAdd(&outacc[(size_t)(row + 8) * DD + col], acc[mt][nt][2]);
            atomicAdd(&outacc[(size_t)(row + 8) * DD + col + 1], acc[mt][nt][3]);
        }
    }
}

// ---------------------------------------------------------------------------
// Edge kernel: warp-per-edge x4, SW pipeline depth 2 over the DRAM-stream
// parts (indices + early atomic + cases). A-gathers (L2-resident, 2 MB) are
// issued in the compute stage. Low regs -> 3 CTAs/SM (24 warps).
// ---------------------------------------------------------------------------
struct EdgeBatch {
    int c[4], t[4];
    int cm, tm, pos;
    float4 cv[4];
};

template <bool IS64>
__device__ __forceinline__ void edge_load4(int e0, int wstart, int wend, int lane,
                                           const void* __restrict__ cur_,
                                           const void* __restrict__ tgt_,
                                           const float* __restrict__ cases,
                                           EdgeBatch& B) {
#pragma unroll
    for (int i = 0; i < 4; i++) {
        int e = (e0 + i < wend) ? e0 + i : wstart;
        if (IS64) {
            B.c[i] = (int)__ldg(&((const long long*)cur_)[e]);
            B.t[i] = (int)__ldg(&((const long long*)tgt_)[e]);
        } else {
            B.c[i] = __ldg(&((const int*)cur_)[e]);
            B.t[i] = __ldg(&((const int*)tgt_)[e]);
        }
    }
    int nb = wend - e0; if (nb > 4) nb = 4;
    B.tm = (lane == 0) ? B.t[0] : (lane == 1) ? B.t[1] : (lane == 2) ? B.t[2] : B.t[3];
    B.cm = (lane == 0) ? B.c[0] : (lane == 1) ? B.c[1] : (lane == 2) ? B.c[2] : B.c[3];
    B.pos = -1;
    if (lane < nb) B.pos = atomicAdd(&g_cursor[B.tm], 1);
#pragma unroll
    for (int i = 0; i < 4; i++) {
        int e = (e0 + i < wend) ? e0 + i : wstart;
        B.cv[i] = __ldg(&((const float4*)(cases + (size_t)e * DD))[lane]);
    }
}

__device__ __forceinline__ void edge_compute4(int e0, int wend, int lane,
                                              EdgeBatch& B) {
    uint2 hu[4], tu[4];
#pragma unroll
    for (int i = 0; i < 4; i++) {
        hu[i] = __ldg(&((const uint2*)(g_Abf + (size_t)B.c[i] * DD))[lane]);
        tu[i] = __ldg(&((const uint2*)(g_Abf + (size_t)B.t[i] * DD))[lane]);
    }
    float sred[4];
#pragma unroll
    for (int i = 0; i < 4; i++) {
        __nv_bfloat162 h01 = *(__nv_bfloat162*)&hu[i].x;
        __nv_bfloat162 h23 = *(__nv_bfloat162*)&hu[i].y;
        __nv_bfloat162 t01 = *(__nv_bfloat162*)&tu[i].x;
        __nv_bfloat162 t23 = *(__nv_bfloat162*)&tu[i].y;
        float dx = __bfloat162float(h01.x) + B.cv[i].x - __bfloat162float(t01.x);
        float dy = __bfloat162float(h01.y) + B.cv[i].y - __bfloat162float(t01.y);
        float dz = __bfloat162float(h23.x) + B.cv[i].z - __bfloat162float(t23.x);
        float dw = __bfloat162float(h23.y) + B.cv[i].w - __bfloat162float(t23.y);
        float s = dx * dx + dy * dy + dz * dz + dw * dw;
#pragma unroll
        for (int o = 16; o > 0; o >>= 1) s += __shfl_xor_sync(0xffffffffu, s, o);
        sred[i] = s;
    }
    int nb = wend - e0; if (nb > 4) nb = 4;
    if (lane < nb && B.pos >= 0 && B.pos < SLOTS) {
        float sm = (lane == 0) ? sred[0] : (lane == 1) ? sred[1]
                   : (lane == 2) ? sred[2] : sred[3];
        float v = __expf(-__fsqrt_rn(sm));
        g_ent[(size_t)B.tm * SLOTS + B.pos] = make_float2(__int_as_float(B.cm), v);
    }
}

template <bool IS64>
__device__ __forceinline__ void edge_body(const void* __restrict__ cur_,
                                          const void* __restrict__ tgt_,
                                          const float* __restrict__ cases,
                                          int E) {
    const int wid = threadIdx.x >> 5, lane = threadIdx.x & 31;
    const int NW = GRIDE * 8;
    const int strip = (E + NW - 1) / NW;
    const int wg = blockIdx.x * 8 + wid;
    int wstart = wg * strip;
    int wend = wstart + strip;
    if (wend > E) wend = E;
    if (wstart >= wend) return;

    EdgeBatch A, B;
    edge_load4<IS64>(wstart, wstart, wend, lane, cur_, tgt_, cases, A);
    for (int e0 = wstart; e0 < wend; e0 += 8) {
        bool hasB = (e0 + 4) < wend;
        if (hasB) edge_load4<IS64>(e0 + 4, wstart, wend, lane, cur_, tgt_, cases, B);
        edge_compute4(e0, wend, lane, A);
        if (!hasB) break;
        bool hasA = (e0 + 8) < wend;
        if (hasA) edge_load4<IS64>(e0 + 8, wstart, wend, lane, cur_, tgt_, cases, A);
        edge_compute4(e0 + 4, wend, lane, B);
        if (!hasA) break;
    }
}

__global__ __launch_bounds__(256, 3)
void edge_kernel(const void* __restrict__ cur_,
                 const void* __restrict__ tgt_,
                 const float* __restrict__ cases,
                 int E) {
    if (g_is64) edge_body<true>(cur_, tgt_, cases, E);
    else        edge_body<false>(cur_, tgt_, cases, E);
}

// ---------------------------------------------------------------------------
// fp32 feat -> bf16 copy for SpMM gathers
// ---------------------------------------------------------------------------
__global__ void featbf_kernel() {
    int i = blockIdx.x * 256 + threadIdx.x;
    float4 v = ((const float4*)g_feat)[i];
    uint2 p;
    p.x = ((uint32_t)__bfloat16_as_ushort(__float2bfloat16_rn(v.y)) << 16)
          | __bfloat16_as_ushort(__float2bfloat16_rn(v.x));
    p.y = ((uint32_t)__bfloat16_as_ushort(__float2bfloat16_rn(v.w)) << 16)
          | __bfloat16_as_ushort(__float2bfloat16_rn(v.z));
    ((uint2*)g_featbf)[i] = p;
}

// ---------------------------------------------------------------------------
// SpMM: block per output row t. out[t][:] = (sum val_i * feat[c_i][:]) /
// (sum val_i + eps) + feat[t][:].  feat gathers in bf16 (L2-resident).
// ---------------------------------------------------------------------------
__global__ __launch_bounds__(128)
void spmm_kernel(float* __restrict__ out) {
    __shared__ float2 ch[256];
    int t = blockIdx.x;
    int tid = threadIdx.x;
    int n = g_cursor[t];
    if (n > SLOTS) n = SLOTS;
    const float2* row = g_ent + (size_t)t * SLOTS;
    float acc = 0.f, rsum = 0.f;
    for (int base = 0; base < n; base += 256) {
        int rem = n - base;
        if (tid < rem) ch[tid] = row[base + tid];
        if (tid + 128 < rem) ch[tid + 128] = row[base + tid + 128];
        __syncthreads();
        int lim = rem < 256 ? rem : 256;
#pragma unroll 8
        for (int j = 0; j < lim; j++) {
            float2 ev = ch[j];
            int c = __float_as_int(ev.x);
            rsum += ev.y;
            acc += ev.y * __bfloat162float(g_featbf[c * DD + tid]);
        }
        __syncthreads();
    }
    out[(size_t)t * DD + tid] = acc / (rsum + EPS) + g_feat[(size_t)t * DD + tid];
}

// ---------------------------------------------------------------------------
extern "C" void kernel_launch(void* const* d_in, const int* in_sizes, int n_in,
                              void* d_out, int out_size) {
    const void* cur = d_in[0];
    const void* tgt = d_in[1];
    const float* A = (const float*)d_in[2];
    const float* cases = (const float*)d_in[3];
    const float* W = (const float*)d_in[4];
    float* out = (float*)d_out;
    int E = in_sizes[3] / DD;

    cudaFuncSetAttribute(gemm_mma_kernel,
                         cudaFuncAttributeMaxDynamicSharedMemorySize, SMEM_GEMM);

    float* p_feat;
    int* p_cursor;
    __nv_bfloat16 *p_Bh, *p_Bl;
    cudaGetSymbolAddress((void**)&p_feat, g_feat);
    cudaGetSymbolAddress((void**)&p_cursor, g_cursor);
    cudaGetSymbolAddress((void**)&p_Bh, g_Bh);
    cudaGetSymbolAddress((void**)&p_Bl, g_Bl);

    cudaMemsetAsync(p_feat, 0, (size_t)NN * DD * sizeof(float));
    cudaMemsetAsync(p_cursor, 0, NN * sizeof(int));

    detect_kernel<<<1, 32>>>((const unsigned int*)cur);
    prep_kernel<<<dim3(NN / 32, DD / 32), dim3(32, 8)>>>(A);
    edge_kernel<<<GRIDE, 256>>>(cur, tgt, cases, E);
    gemm_mma_kernel<<<256, 256, SMEM_GEMM>>>(W, p_Bh, p_Bl, p_feat);
    featbf_kernel<<<512, 256>>>();
    spmm_kernel<<<NN, 128>>>(out);
}

// round 14
// speedup vs baseline: 1.0707x; 1.0707x over previous
#include <cuda_runtime.h>
#include <cuda_bf16.h>
#include <cstdint>
#include <cstddef>

#define NN 4096
#define DD 128
#define EPS 1e-12f
#define SLOTS 512            // per-row edge slots (mean 244, 17-sigma safe)

#define NGEMM 256            // gemm tile-blocks (64 M-tiles x 4 K-splits)
#define GRID_FUSED 2048      // total blocks; 1792 edge blocks

// ---------------- scratch (__device__ globals; no allocs allowed) ----------
__device__ float g_feat[NN * DD];                       // W @ activities (fp32)
__device__ __nv_bfloat16 g_featbf[NN * DD];             // bf16 copy for SpMM gathers
__device__ __nv_bfloat16 g_Abf[NN * DD];                // activities bf16 (edge gathers)
__device__ __nv_bfloat16 g_Bh[DD * NN], g_Bl[DD * NN];  // activities^T split [N][K]
__device__ float2 g_ent[(size_t)NN * SLOTS];            // (col,val) per row, 16 MB
__device__ int g_cursor[NN];
__device__ int g_is64;

// ---------------------------------------------------------------------------
// detect: independent loads (MLP 64), no serial break chain
// ---------------------------------------------------------------------------
__global__ void detect_kernel(const unsigned int* __restrict__ w) {
    int lane = threadIdx.x;
    unsigned int acc = w[2 * lane + 1] | w[2 * (lane + 32) + 1];
#pragma unroll
    for (int o = 16; o > 0; o >>= 1) acc |= __shfl_xor_sync(0xffffffffu, acc, o);
    if (lane == 0) g_is64 = (acc == 0u) ? 1 : 0;
}

// ---------------------------------------------------------------------------
// prep: A [4096,128] fp32 -> g_Bh/g_Bl [128,4096] split ([N][K]) + g_Abf bf16
// ---------------------------------------------------------------------------
__global__ void prep_kernel(const float* __restrict__ src) {
    __shared__ float tile[32][33];
    int k0 = blockIdx.x * 32, n0 = blockIdx.y * 32;
    int tx = threadIdx.x, ty = threadIdx.y;
#pragma unroll
    for (int i = 0; i < 4; i++) {
        size_t idx = (size_t)(k0 + ty + i * 8) * DD + n0 + tx;
        float v = src[idx];
        tile[ty + i * 8][tx] = v;
        g_Abf[idx] = __float2bfloat16_rn(v);
    }
    __syncthreads();
#pragma unroll
    for (int i = 0; i < 4; i++) {
        float x = tile[tx][ty + i * 8];
        __nv_bfloat16 h = __float2bfloat16_rn(x);
        __nv_bfloat16 l = __float2bfloat16_rn(x - __bfloat162float(h));
        size_t o = (size_t)(n0 + ty + i * 8) * NN + k0 + tx;
        g_Bh[o] = h;
        g_Bl[o] = l;
    }
}

// ---------------------------------------------------------------------------
#define PITCHB 144           // bytes per smem row (72 bf16: +8 pad, conflict-free)
#define SM_AH 0
#define SM_AL (64 * PITCHB)
#define SM_BH (2 * 64 * PITCHB)
#define SM_BL (2 * 64 * PITCHB + 128 * PITCHB)
#define SMEM_GEMM (2 * 64 * PITCHB + 2 * 128 * PITCHB)   // 55296 B

__device__ __forceinline__ void mma_bf16(float* c, const uint32_t* a, const uint32_t* b) {
    asm volatile(
        "mma.sync.aligned.m16n8k16.row.col.f32.bf16.bf16.f32 "
        "{%0,%1,%2,%3}, {%4,%5,%6,%7}, {%8,%9}, {%0,%1,%2,%3};"
        : "+f"(c[0]), "+f"(c[1]), "+f"(c[2]), "+f"(c[3])
        : "r"(a[0]), "r"(a[1]), "r"(a[2]), "r"(a[3]), "r"(b[0]), "r"(b[1]));
}

// ---------------------------------------------------------------------------
// Gemm tile body: g_feat[m0:m0+64][:] += W_tile @ B^T  (split-K partials)
// ---------------------------------------------------------------------------
__device__ __forceinline__ void gemm_tile(char* smem, int tile,
                                          const float* __restrict__ Amat,
                                          const __nv_bfloat16* __restrict__ Bh,
                                          const __nv_bfloat16* __restrict__ Bl,
                                          float* __restrict__ outacc) {
    const int tid = threadIdx.x;
    const int wid = tid >> 5, lane = tid & 31;
    const int warp_m = wid >> 2, warp_n = wid & 3;   // 2 x 4
    const int lr = lane >> 2, lc = lane & 3;
    const int m0 = (tile >> 2) * 64;
    const int kbase = (tile & 3) * 1024;

    const int a_row = tid >> 4;
    const int a_c4 = tid & 15;

    float acc[2][4][4];
#pragma unroll
    for (int i = 0; i < 2; i++)
#pragma unroll
        for (int j = 0; j < 4; j++)
#pragma unroll
            for (int q = 0; q < 4; q++) acc[i][j][q] = 0.f;

    for (int ch = 0; ch < 16; ch++) {
        int k0 = kbase + ch * 64;
        float4 av[4];
#pragma unroll
        for (int i = 0; i < 4; i++)
            av[i] = *(const float4*)&Amat[(size_t)(m0 + a_row + i * 16) * NN + k0 + a_c4 * 4];
        uint4 bhv[4], blv[4];
#pragma unroll
        for (int i = 0; i < 4; i++) {
            int idx = tid + i * 256;
            int n = idx >> 3, q = idx & 7;
            size_t byt = ((size_t)n * NN + k0) * 2 + q * 16;
            bhv[i] = *(const uint4*)((const char*)Bh + byt);
            blv[i] = *(const uint4*)((const char*)Bl + byt);
        }
        if (ch > 0) __syncthreads();
#pragma unroll
        for (int i = 0; i < 4; i++) {
            float4 v = av[i];
            __nv_bfloat16 h0 = __float2bfloat16_rn(v.x);
            __nv_bfloat16 h1 = __float2bfloat16_rn(v.y);
            __nv_bfloat16 h2 = __float2bfloat16_rn(v.z);
            __nv_bfloat16 h3 = __float2bfloat16_rn(v.w);
            __nv_bfloat16 l0 = __float2bfloat16_rn(v.x - __bfloat162float(h0));
            __nv_bfloat16 l1 = __float2bfloat16_rn(v.y - __bfloat162float(h1));
            __nv_bfloat16 l2 = __float2bfloat16_rn(v.z - __bfloat162float(h2));
            __nv_bfloat16 l3 = __float2bfloat16_rn(v.w - __bfloat162float(h3));
            uint2 hp, lp;
            hp.x = ((uint32_t)__bfloat16_as_ushort(h1) << 16) | __bfloat16_as_ushort(h0);
            hp.y = ((uint32_t)__bfloat16_as_ushort(h3) << 16) | __bfloat16_as_ushort(h2);
            lp.x = ((uint32_t)__bfloat16_as_ushort(l1) << 16) | __bfloat16_as_ushort(l0);
            lp.y = ((uint32_t)__bfloat16_as_ushort(l3) << 16) | __bfloat16_as_ushort(l2);
            uint32_t off = (uint32_t)(a_row + i * 16) * PITCHB + a_c4 * 8;
            *(uint2*)(smem + SM_AH + off) = hp;
            *(uint2*)(smem + SM_AL + off) = lp;
        }
#pragma unroll
        for (int i = 0; i < 4; i++) {
            int idx = tid + i * 256;
            int n = idx >> 3, q = idx & 7;
            uint32_t off = (uint32_t)n * PITCHB + q * 16;
            *(uint4*)(smem + SM_BH + off) = bhv[i];
            *(uint4*)(smem + SM_BL + off) = blv[i];
        }
        __syncthreads();
#pragma unroll
        for (int k16 = 0; k16 < 4; k16++) {
            uint32_t a_h[2][4], a_l[2][4];
#pragma unroll
            for (int mt = 0; mt < 2; mt++) {
                uint32_t base = (uint32_t)(warp_m * 32 + mt * 16 + lr) * PITCHB
                                + k16 * 32 + lc * 4;
                a_h[mt][0] = *(const uint32_t*)(smem + SM_AH + base);
                a_h[mt][1] = *(const uint32_t*)(smem + SM_AH + base + 8 * PITCHB);
                a_h[mt][2] = *(const uint32_t*)(smem + SM_AH + base + 16);
                a_h[mt][3] = *(const uint32_t*)(smem + SM_AH + base + 8 * PITCHB + 16);
                a_l[mt][0] = *(const uint32_t*)(smem + SM_AL + base);
                a_l[mt][1] = *(const uint32_t*)(smem + SM_AL + base + 8 * PITCHB);
                a_l[mt][2] = *(const uint32_t*)(smem + SM_AL + base + 16);
                a_l[mt][3] = *(const uint32_t*)(smem + SM_AL + base + 8 * PITCHB + 16);
            }
#pragma unroll
            for (int nt = 0; nt < 4; nt++) {
                uint32_t b_h[2], b_l[2];
                uint32_t base = (uint32_t)(warp_n * 32 + nt * 8 + lr) * PITCHB
                                + k16 * 32 + lc * 4;
                b_h[0] = *(const uint32_t*)(smem + SM_BH + base);
                b_h[1] = *(const uint32_t*)(smem + SM_BH + base + 16);
                b_l[0] = *(const uint32_t*)(smem + SM_BL + base);
                b_l[1] = *(const uint32_t*)(smem + SM_BL + base + 16);
#pragma unroll
                for (int mt = 0; mt < 2; mt++) {
                    mma_bf16(acc[mt][nt], a_h[mt], b_h);
                    mma_bf16(acc[mt][nt], a_h[mt], b_l);
                    mma_bf16(acc[mt][nt], a_l[mt], b_h);
                }
            }
        }
    }
#pragma unroll
    for (int mt = 0; mt < 2; mt++) {
#pragma unroll
        for (int nt = 0; nt < 4; nt++) {
            int row = (tile >> 2) * 64 + warp_m * 32 + mt * 16 + lr;
            int col = warp_n * 32 + nt * 8 + lc * 2;
            atomicAdd(&outacc[(size_t)row * DD + col], acc[mt][nt][0]);
            atomicAdd(&outacc[(size_t)row * DD + col + 1], acc[mt][nt][1]);
            atomicAdd(&outacc[(size_t)(row + 8) * DD + col], acc[mt][nt][2]);
            atomicAdd(&outacc[(size_t)(row + 8) * DD + col + 1], acc[mt][nt][3]);
        }
    }
}

// ---------------------------------------------------------------------------
// Edge batch: warp-per-edge x4, software-pipelined (depth 2), full prefetch.
// ---------------------------------------------------------------------------
struct EdgeBatch {
    int cm, tm, pos;
    uint2 hu[4], tu[4];
    float4 cv[4];
};

template <bool IS64>
__device__ __forceinline__ void edge_load4(int e0, int wstart, int wend, int lane,
                                           const void* __restrict__ cur_,
                                           const void* __restrict__ tgt_,
                                           const float* __restrict__ cases,
                                           EdgeBatch& B) {
    int c[4], t[4];
#pragma unroll
    for (int i = 0; i < 4; i++) {
        int e = (e0 + i < wend) ? e0 + i : wstart;
        if (IS64) {
            c[i] = (int)__ldg(&((const long long*)cur_)[e]);
            t[i] = (int)__ldg(&((const long long*)tgt_)[e]);
        } else {
            c[i] = __ldg(&((const int*)cur_)[e]);
            t[i] = __ldg(&((const int*)tgt_)[e]);
        }
    }
    int nb = wend - e0; if (nb > 4) nb = 4;
    B.tm = (lane == 0) ? t[0] : (lane == 1) ? t[1] : (lane == 2) ? t[2] : t[3];
    B.cm = (lane == 0) ? c[0] : (lane == 1) ? c[1] : (lane == 2) ? c[2] : c[3];
    B.pos = -1;
    if (lane < nb) B.pos = atomicAdd(&g_cursor[B.tm], 1);
#pragma unroll
    for (int i = 0; i < 4; i++) {
        B.hu[i] = __ldg(&((const uint2*)(g_Abf + (size_t)c[i] * DD))[lane]);
        B.tu[i] = __ldg(&((const uint2*)(g_Abf + (size_t)t[i] * DD))[lane]);
        int e = (e0 + i < wend) ? e0 + i : wstart;
        B.cv[i] = __ldg(&((const float4*)(cases + (size_t)e * DD))[lane]);
    }
}

__device__ __forceinline__ void edge_compute4(int e0, int wend, int lane,
                                              EdgeBatch& B) {
    float sred[4];
#pragma unroll
    for (int i = 0; i < 4; i++) {
        __nv_bfloat162 h01 = *(__nv_bfloat162*)&B.hu[i].x;
        __nv_bfloat162 h23 = *(__nv_bfloat162*)&B.hu[i].y;
        __nv_bfloat162 t01 = *(__nv_bfloat162*)&B.tu[i].x;
        __nv_bfloat162 t23 = *(__nv_bfloat162*)&B.tu[i].y;
        float dx = __bfloat162float(h01.x) + B.cv[i].x - __bfloat162float(t01.x);
        float dy = __bfloat162float(h01.y) + B.cv[i].y - __bfloat162float(t01.y);
        float dz = __bfloat162float(h23.x) + B.cv[i].z - __bfloat162float(t23.x);
        float dw = __bfloat162float(h23.y) + B.cv[i].w - __bfloat162float(t23.y);
        float s = dx * dx + dy * dy + dz * dz + dw * dw;
#pragma unroll
        for (int o = 16; o > 0; o >>= 1) s += __shfl_xor_sync(0xffffffffu, s, o);
        sred[i] = s;
    }
    int nb = wend - e0; if (nb > 4) nb = 4;
    if (lane < nb && B.pos >= 0 && B.pos < SLOTS) {
        float sm = (lane == 0) ? sred[0] : (lane == 1) ? sred[1]
                   : (lane == 2) ? sred[2] : sred[3];
        float v = __expf(-__fsqrt_rn(sm));
        g_ent[(size_t)B.tm * SLOTS + B.pos] = make_float2(__int_as_float(B.cm), v);
    }
}

template <bool IS64>
__device__ __forceinline__ void edge_strip(int rank,
                                           const void* __restrict__ cur_,
                                           const void* __restrict__ tgt_,
                                           const float* __restrict__ cases,
                                           int E) {
    const int wid = threadIdx.x >> 5, lane = threadIdx.x & 31;
    const int NW = (GRID_FUSED - NGEMM) * 8;
    const int strip = (E + NW - 1) / NW;
    const int wg = rank * 8 + wid;
    int wstart = wg * strip;
    int wend = wstart + strip;
    if (wend > E) wend = E;
    if (wstart >= wend) return;

    EdgeBatch A, B;
    edge_load4<IS64>(wstart, wstart, wend, lane, cur_, tgt_, cases, A);
    for (int e0 = wstart; e0 < wend; e0 += 8) {
        bool hasB = (e0 + 4) < wend;
        if (hasB) edge_load4<IS64>(e0 + 4, wstart, wend, lane, cur_, tgt_, cases, B);
        edge_compute4(e0, wend, lane, A);
        if (!hasB) break;
        bool hasA = (e0 + 8) < wend;
        if (hasA) edge_load4<IS64>(e0 + 8, wstart, wend, lane, cur_, tgt_, cases, A);
        edge_compute4(e0 + 4, wend, lane, B);
        if (!hasA) break;
    }
}

// ---------------------------------------------------------------------------
// Fused kernel: blocks 0..511 alternate gemm/edge; 512+ are edge strips.
// ---------------------------------------------------------------------------
__global__ __launch_bounds__(256, 2)
void fused_kernel(const float* __restrict__ Wm,
                  const __nv_bfloat16* __restrict__ Bh,
                  const __nv_bfloat16* __restrict__ Bl,
                  float* __restrict__ outacc,
                  const void* __restrict__ cur_,
                  const void* __restrict__ tgt_,
                  const float* __restrict__ cases,
                  int E) {
    extern __shared__ char smem[];
    int b = blockIdx.x;
    if (b < 512 && (b & 1) == 0) {
        gemm_tile(smem, b >> 1, Wm, Bh, Bl, outacc);
    } else {
        int rank = (b < 512) ? (b >> 1) : (b - NGEMM);
        if (g_is64) edge_strip<true>(rank, cur_, tgt_, cases, E);
        else        edge_strip<false>(rank, cur_, tgt_, cases, E);
    }
}

// ---------------------------------------------------------------------------
// fp32 feat -> bf16 copy for SpMM gathers
// ---------------------------------------------------------------------------
__global__ void featbf_kernel() {
    int i = blockIdx.x * 256 + threadIdx.x;
    float4 v = ((const float4*)g_feat)[i];
    uint2 p;
    p.x = ((uint32_t)__bfloat16_as_ushort(__float2bfloat16_rn(v.y)) << 16)
          | __bfloat16_as_ushort(__float2bfloat16_rn(v.x));
    p.y = ((uint32_t)__bfloat16_as_ushort(__float2bfloat16_rn(v.w)) << 16)
          | __bfloat16_as_ushort(__float2bfloat16_rn(v.z));
    ((uint2*)g_featbf)[i] = p;
}

// ---------------------------------------------------------------------------
// SpMM: block per output row t. out[t][:] = (sum val_i * feat[c_i][:]) /
// (sum val_i + eps) + feat[t][:].  feat gathers in bf16 (L2-resident).
// ---------------------------------------------------------------------------
__global__ __launch_bounds__(128)
void spmm_kernel(float* __restrict__ out) {
    __shared__ float2 ch[256];
    int t = blockIdx.x;
    int tid = threadIdx.x;
    int n = g_cursor[t];
    if (n > SLOTS) n = SLOTS;
    const float2* row = g_ent + (size_t)t * SLOTS;
    float acc = 0.f, rsum = 0.f;
    for (int base = 0; base < n; base += 256) {
        int rem = n - base;
        if (tid < rem) ch[tid] = row[base + tid];
        if (tid + 128 < rem) ch[tid + 128] = row[base + tid + 128];
        __syncthreads();
        int lim = rem < 256 ? rem : 256;
#pragma unroll 8
        for (int j = 0; j < lim; j++) {
            float2 ev = ch[j];
            int c = __float_as_int(ev.x);
            rsum += ev.y;
            acc += ev.y * __bfloat162float(g_featbf[c * DD + tid]);
        }
        __syncthreads();
    }
    out[(size_t)t * DD + tid] = acc / (rsum + EPS) + g_feat[(size_t)t * DD + tid];
}

// ---------------------------------------------------------------------------
extern "C" void kernel_launch(void* const* d_in, const int* in_sizes, int n_in,
                              void* d_out, int out_size) {
    const void* cur = d_in[0];
    const void* tgt = d_in[1];
    const float* A = (const float*)d_in[2];
    const float* cases = (const float*)d_in[3];
    const float* W = (const float*)d_in[4];
    float* out = (float*)d_out;
    int E = in_sizes[3] / DD;

    cudaFuncSetAttribute(fused_kernel,
                         cudaFuncAttributeMaxDynamicSharedMemorySize, SMEM_GEMM);

    float* p_feat;
    int* p_cursor;
    __nv_bfloat16 *p_Bh, *p_Bl;
    cudaGetSymbolAddress((void**)&p_feat, g_feat);
    cudaGetSymbolAddress((void**)&p_cursor, g_cursor);
    cudaGetSymbolAddress((void**)&p_Bh, g_Bh);
    cudaGetSymbolAddress((void**)&p_Bl, g_Bl);

    cudaMemsetAsync(p_feat, 0, (size_t)NN * DD * sizeof(float));
    cudaMemsetAsync(p_cursor, 0, NN * sizeof(int));

    detect_kernel<<<1, 32>>>((const unsigned int*)cur);
    prep_kernel<<<dim3(NN / 32, DD / 32), dim3(32, 8)>>>(A);
    fused_kernel<<<GRID_FUSED, 256, SMEM_GEMM>>>(W, p_Bh, p_Bl, p_feat,
                                                 cur, tgt, cases, E);
    featbf_kernel<<<512, 256>>>();
    spmm_kernel<<<NN, 128>>>(out);
}